// round 6
// baseline (speedup 1.0000x reference)
#include <cuda_runtime.h>
#include <cuda_bf16.h>
#include <cstdint>
#include <math.h>

#define BB 2
#define SS 2048
#define DD 1024
#define HH 16
#define HDim 64
#define NHZ (BB*HH)

// Packed scratch: u32 = bf16_hi | bf16_lo<<16
__device__ uint32_t g_xq[4194304], g_xk[4194304], g_xv[4194304];
__device__ uint32_t g_wq[1048576], g_wk[1048576], g_wv[1048576], g_wo[1048576];
__device__ uint32_t g_qp[4194304];   // Q packed (z,s,hd)
__device__ uint32_t g_kp[4194304];   // K packed (z,s,hd)
__device__ uint32_t g_vt[4194304];   // V packed transposed (z,hd,s)
__device__ uint32_t g_aop[4194304];  // attn_output packed (b,s,d)
__device__ float g_mx[NHZ * SS];     // per-row softmax max
__device__ float g_rs[NHZ * SS];     // per-row 1/sum

__device__ __forceinline__ void mma_bf16(float d[4], const uint32_t a[4], const uint32_t b[2]) {
    asm volatile(
        "mma.sync.aligned.m16n8k16.row.col.f32.bf16.bf16.f32 "
        "{%0,%1,%2,%3}, {%4,%5,%6,%7}, {%8,%9}, {%0,%1,%2,%3};"
        : "+f"(d[0]), "+f"(d[1]), "+f"(d[2]), "+f"(d[3])
        : "r"(a[0]), "r"(a[1]), "r"(a[2]), "r"(a[3]), "r"(b[0]), "r"(b[1]));
}
__device__ __forceinline__ uint32_t packf(float x) {
    __nv_bfloat16 h = __float2bfloat16(x);
    __nv_bfloat16 l = __float2bfloat16(x - __bfloat162float(h));
    return (uint32_t)__bfloat16_as_ushort(h) | ((uint32_t)__bfloat16_as_ushort(l) << 16);
}
__device__ __forceinline__ void cpa16(uint32_t dst, const void* src) {
    asm volatile("cp.async.cg.shared.global [%0], [%1], 16;" :: "r"(dst), "l"(src));
}
#define CP_COMMIT() asm volatile("cp.async.commit_group;" ::: "memory")
#define CP_WAIT1() asm volatile("cp.async.wait_group 1;" ::: "memory")
#define CP_WAIT0() asm volatile("cp.async.wait_group 0;" ::: "memory")

__device__ __forceinline__ void lda_pk(const uint32_t* S, int lda, int r, int ks, int l,
                                       uint32_t ah[4], uint32_t al[4]) {
    const uint32_t* p = S + (r + (l >> 2)) * lda + ks * 16 + 2 * (l & 3);
    uint2 q0 = *(const uint2*)p;
    uint2 q1 = *(const uint2*)(p + 8);
    uint2 q2 = *(const uint2*)(p + 8 * lda);
    uint2 q3 = *(const uint2*)(p + 8 * lda + 8);
    ah[0] = __byte_perm(q0.x, q0.y, 0x5410); al[0] = __byte_perm(q0.x, q0.y, 0x7632);
    ah[1] = __byte_perm(q2.x, q2.y, 0x5410); al[1] = __byte_perm(q2.x, q2.y, 0x7632);
    ah[2] = __byte_perm(q1.x, q1.y, 0x5410); al[2] = __byte_perm(q1.x, q1.y, 0x7632);
    ah[3] = __byte_perm(q3.x, q3.y, 0x5410); al[3] = __byte_perm(q3.x, q3.y, 0x7632);
}
__device__ __forceinline__ void ldb_pk(const uint32_t* S, int lda, int n, int ks, int l,
                                       uint32_t bh[2], uint32_t bl[2]) {
    const uint32_t* p = S + (n + (l >> 2)) * lda + ks * 16 + 2 * (l & 3);
    uint2 q0 = *(const uint2*)p;
    uint2 q1 = *(const uint2*)(p + 8);
    bh[0] = __byte_perm(q0.x, q0.y, 0x5410); bl[0] = __byte_perm(q0.x, q0.y, 0x7632);
    bh[1] = __byte_perm(q1.x, q1.y, 0x5410); bl[1] = __byte_perm(q1.x, q1.y, 0x7632);
}

// Batched packs: blockIdx.y selects the array.
__global__ void pack3_kernel(const float4* s0, const float4* s1, const float4* s2,
                             uint4* d0, uint4* d1, uint4* d2, int n4) {
    int i = blockIdx.x * 256 + threadIdx.x;
    const float4* s = (blockIdx.y == 0) ? s0 : (blockIdx.y == 1) ? s1 : s2;
    uint4* d = (blockIdx.y == 0) ? d0 : (blockIdx.y == 1) ? d1 : d2;
    if (i < n4) {
        float4 v = s[i];
        d[i] = make_uint4(packf(v.x), packf(v.y), packf(v.z), packf(v.w));
    }
}
__global__ void pack4_kernel(const float4* s0, const float4* s1, const float4* s2, const float4* s3,
                             uint4* d0, uint4* d1, uint4* d2, uint4* d3, int n4) {
    int i = blockIdx.x * 256 + threadIdx.x;
    const float4* s = (blockIdx.y == 0) ? s0 : (blockIdx.y == 1) ? s1
                    : (blockIdx.y == 2) ? s2 : s3;
    uint4* d = (blockIdx.y == 0) ? d0 : (blockIdx.y == 1) ? d1
             : (blockIdx.y == 2) ? d2 : d3;
    if (i < n4) {
        float4 v = s[i];
        d[i] = make_uint4(packf(v.x), packf(v.y), packf(v.z), packf(v.w));
    }
}

// ---------------------------------------------------------------------------
// Projection: Y = X@W^T + bias. Tile 128x64, BK=32, 8 warps (4m x 2n).
// MODE 0: packed (z,s,hd); MODE 1: packed transposed (z,hd,s); MODE 2: fp32 rm.
// ---------------------------------------------------------------------------
#define PJ_AW (128*40)
#define PJ_BW (64*40)
#define PJ_SM ((2*PJ_AW + 2*PJ_BW)*4)

template <int MODE>
__global__ __launch_bounds__(256, 2) void proj_mma(
    const uint32_t* __restrict__ Xp, const uint32_t* __restrict__ Wp,
    const float* __restrict__ bias, void* __restrict__ Yv)
{
    extern __shared__ uint32_t sm[];
    const uint32_t sb = (uint32_t)__cvta_generic_to_shared(sm);
    const int tid = threadIdx.x, w = tid >> 5, l = tid & 31;
    const int m0 = blockIdx.y << 7, n0 = blockIdx.x << 6;
    const int wm = (w & 3) << 5, wn = (w >> 2) << 5;

    auto stage = [&](int c) {
        const int bi = c & 1;
        const uint32_t aB = sb + bi * (PJ_AW * 4);
        #pragma unroll
        for (int i = 0; i < 4; i++) {
            int g = tid + (i << 8), row = g >> 3, q = g & 7;
            cpa16(aB + (uint32_t)(row * 40 + q * 4) * 4,
                  Xp + (size_t)(m0 + row) * DD + c * 32 + q * 4);
        }
        const uint32_t bB = sb + (2 * PJ_AW + bi * PJ_BW) * 4;
        #pragma unroll
        for (int i = 0; i < 2; i++) {
            int g = tid + (i << 8), row = g >> 3, q = g & 7;
            cpa16(bB + (uint32_t)(row * 40 + q * 4) * 4,
                  Wp + (size_t)(n0 + row) * DD + c * 32 + q * 4);
        }
        CP_COMMIT();
    };
    stage(0); stage(1);

    float acc[2][4][4] = {};
    for (int c = 0; c < 32; c++) {
        if (c < 31) CP_WAIT1(); else CP_WAIT0();
        __syncthreads();
        const uint32_t* As = sm + (c & 1) * PJ_AW;
        const uint32_t* Bs = sm + 2 * PJ_AW + (c & 1) * PJ_BW;
        #pragma unroll
        for (int ks = 0; ks < 2; ks++) {
            uint32_t ah[2][4], al[2][4];
            lda_pk(As, 40, wm, ks, l, ah[0], al[0]);
            lda_pk(As, 40, wm + 16, ks, l, ah[1], al[1]);
            #pragma unroll
            for (int ni = 0; ni < 4; ni++) {
                uint32_t bh[2], bl[2];
                ldb_pk(Bs, 40, wn + ni * 8, ks, l, bh, bl);
                #pragma unroll
                for (int mi = 0; mi < 2; mi++) {
                    mma_bf16(acc[mi][ni], ah[mi], bh);
                    mma_bf16(acc[mi][ni], ah[mi], bl);
                    mma_bf16(acc[mi][ni], al[mi], bh);
                }
            }
        }
        __syncthreads();
        if (c + 2 < 32) stage(c + 2);
    }

    #pragma unroll
    for (int mi = 0; mi < 2; mi++) {
        #pragma unroll
        for (int ni = 0; ni < 4; ni++) {
            const int r = m0 + wm + mi * 16 + (l >> 2);
            const int cc = n0 + wn + ni * 8 + 2 * (l & 3);
            const float b0 = __ldg(bias + cc), b1 = __ldg(bias + cc + 1);
            float y00 = acc[mi][ni][0] + b0, y01 = acc[mi][ni][1] + b1;
            float y10 = acc[mi][ni][2] + b0, y11 = acc[mi][ni][3] + b1;
            if (MODE == 2) {
                float* O = (float*)Yv;
                *(float2*)(O + (size_t)r * DD + cc) = make_float2(y00, y01);
                *(float2*)(O + (size_t)(r + 8) * DD + cc) = make_float2(y10, y11);
            } else {
                uint32_t* Y = (uint32_t*)Yv;
                const int b_ = r >> 11, s = r & (SS - 1), h = cc >> 6, hd = cc & 63;
                if (MODE == 0) {
                    size_t zb = (size_t)(b_ * HH + h) * SS;
                    *(uint2*)(Y + (zb + s) * HDim + hd) = make_uint2(packf(y00), packf(y01));
                    *(uint2*)(Y + (zb + s + 8) * HDim + hd) = make_uint2(packf(y10), packf(y11));
                } else {
                    size_t zb = (size_t)(b_ * HH + h) * HDim;
                    Y[(zb + hd) * SS + s]         = packf(y00);
                    Y[(zb + hd + 1) * SS + s]     = packf(y01);
                    Y[(zb + hd) * SS + s + 8]     = packf(y10);
                    Y[(zb + hd + 1) * SS + s + 8] = packf(y11);
                }
            }
        }
    }
}

// ---------------------------------------------------------------------------
// Scores + online softmax stats. CTA = 64-row strip over all 16 n-tiles.
// Writes scaled raw scores to P, plus per-row max and 1/sum.
// 8 warps (2m x 4n), warp 32x32.
// ---------------------------------------------------------------------------
#define SC_AW (64*72)
#define SC_BW (128*72)
#define SC_STATW (SC_AW + 2*SC_BW)
#define SC_SM ((SC_STATW + 512)*4)

__global__ __launch_bounds__(256) void scores_mma(
    const uint32_t* __restrict__ Qp, const uint32_t* __restrict__ Kp,
    float* __restrict__ P, float* __restrict__ gmx, float* __restrict__ grs)
{
    extern __shared__ uint32_t sm[];
    const uint32_t sb = (uint32_t)__cvta_generic_to_shared(sm);
    float* sm_m = (float*)(sm + SC_STATW);        // [4][64]
    float* sm_s = sm_m + 256;                     // [4][64]
    const int tid = threadIdx.x, w = tid >> 5, l = tid & 31;
    const int z = blockIdx.y, m0 = blockIdx.x << 6;
    const int wm = (w & 1) << 5, wn = (w >> 1) << 5;

    auto stageB = [&](int nt) {
        const uint32_t bB = sb + (SC_AW + (nt & 1) * SC_BW) * 4;
        #pragma unroll
        for (int i = 0; i < 8; i++) {
            int g = tid + (i << 8), row = g >> 4, q = g & 15;
            cpa16(bB + (uint32_t)(row * 72 + q * 4) * 4,
                  Kp + ((size_t)z * SS + nt * 128 + row) * HDim + q * 4);
        }
    };
    #pragma unroll
    for (int i = 0; i < 4; i++) {
        int g = tid + (i << 8), row = g >> 4, q = g & 15;
        cpa16(sb + (uint32_t)(row * 72 + q * 4) * 4,
              Qp + ((size_t)z * SS + m0 + row) * HDim + q * 4);
    }
    stageB(0); CP_COMMIT();
    stageB(1); CP_COMMIT();

    float rm[4] = {-1e30f, -1e30f, -1e30f, -1e30f};
    float rs[4] = {0.f, 0.f, 0.f, 0.f};

    float* Pz = P + (size_t)z * SS * SS;
    for (int nt = 0; nt < 16; nt++) {
        if (nt < 15) CP_WAIT1(); else CP_WAIT0();
        __syncthreads();
        const uint32_t* Bs = sm + SC_AW + (nt & 1) * SC_BW;
        float acc[2][4][4] = {};
        #pragma unroll
        for (int ks = 0; ks < 4; ks++) {
            uint32_t ah[2][4], al[2][4];
            lda_pk(sm, 72, wm, ks, l, ah[0], al[0]);
            lda_pk(sm, 72, wm + 16, ks, l, ah[1], al[1]);
            #pragma unroll
            for (int ni = 0; ni < 4; ni++) {
                uint32_t bh[2], bl[2];
                ldb_pk(Bs, 72, wn + ni * 8, ks, l, bh, bl);
                #pragma unroll
                for (int mi = 0; mi < 2; mi++) {
                    mma_bf16(acc[mi][ni], ah[mi], bh);
                    mma_bf16(acc[mi][ni], ah[mi], bl);
                    mma_bf16(acc[mi][ni], al[mi], bh);
                }
            }
        }
        __syncthreads();
        if (nt + 2 < 16) { stageB(nt + 2); CP_COMMIT(); }

        // scale, write raw, update online row stats
        #pragma unroll
        for (int mi = 0; mi < 2; mi++)
            #pragma unroll
            for (int ni = 0; ni < 4; ni++)
                #pragma unroll
                for (int j = 0; j < 4; j++) acc[mi][ni][j] *= 0.125f;

        #pragma unroll
        for (int t = 0; t < 4; t++) {     // t = mi*2 + half
            const int mi = t >> 1, hf = t & 1;
            float v0 = acc[mi][0][hf*2], v1 = acc[mi][0][hf*2+1];
            float v2 = acc[mi][1][hf*2], v3 = acc[mi][1][hf*2+1];
            float v4 = acc[mi][2][hf*2], v5 = acc[mi][2][hf*2+1];
            float v6 = acc[mi][3][hf*2], v7 = acc[mi][3][hf*2+1];
            float tm = fmaxf(fmaxf(fmaxf(v0, v1), fmaxf(v2, v3)),
                             fmaxf(fmaxf(v4, v5), fmaxf(v6, v7)));
            tm = fmaxf(tm, __shfl_xor_sync(~0u, tm, 1));
            tm = fmaxf(tm, __shfl_xor_sync(~0u, tm, 2));
            const float mnew = fmaxf(rm[t], tm);
            float ps = __expf(v0 - mnew) + __expf(v1 - mnew) + __expf(v2 - mnew)
                     + __expf(v3 - mnew) + __expf(v4 - mnew) + __expf(v5 - mnew)
                     + __expf(v6 - mnew) + __expf(v7 - mnew);
            ps += __shfl_xor_sync(~0u, ps, 1);
            ps += __shfl_xor_sync(~0u, ps, 2);
            rs[t] = rs[t] * __expf(rm[t] - mnew) + ps;
            rm[t] = mnew;
        }

        #pragma unroll
        for (int mi = 0; mi < 2; mi++) {
            #pragma unroll
            for (int ni = 0; ni < 4; ni++) {
                const int r = m0 + wm + mi * 16 + (l >> 2);
                const int cc = nt * 128 + wn + ni * 8 + 2 * (l & 3);
                *(float2*)(Pz + (size_t)r * SS + cc) =
                    make_float2(acc[mi][ni][0], acc[mi][ni][1]);
                *(float2*)(Pz + (size_t)(r + 8) * SS + cc) =
                    make_float2(acc[mi][ni][2], acc[mi][ni][3]);
            }
        }
    }

    // merge per-warp-group stats (4 n-warps per row group)
    if ((l & 3) == 0) {
        #pragma unroll
        for (int t = 0; t < 4; t++) {
            const int rl = wm + (t >> 1) * 16 + (t & 1) * 8 + (l >> 2);
            sm_m[(w >> 1) * 64 + rl] = rm[t];
            sm_s[(w >> 1) * 64 + rl] = rs[t];
        }
    }
    __syncthreads();
    if (tid < 64) {
        float m0v = sm_m[tid],       s0v = sm_s[tid];
        float m1v = sm_m[64 + tid],  s1v = sm_s[64 + tid];
        float m2v = sm_m[128 + tid], s2v = sm_s[128 + tid];
        float m3v = sm_m[192 + tid], s3v = sm_s[192 + tid];
        float M = fmaxf(fmaxf(m0v, m1v), fmaxf(m2v, m3v));
        float S = s0v * __expf(m0v - M) + s1v * __expf(m1v - M)
                + s2v * __expf(m2v - M) + s3v * __expf(m3v - M);
        gmx[(size_t)z * SS + m0 + tid] = M;
        grs[(size_t)z * SS + m0 + tid] = 1.0f / S;
    }
}

// ---------------------------------------------------------------------------
// AV: normalizes P in place (w = exp(p-m)*invS), writes normalized attn
// weights back to gmem, feeds w into MMA. Tile 128x64, BK=64.
// ---------------------------------------------------------------------------
#define AV_AW (128*72)
#define AV_BW (64*72)
#define AV_SM ((AV_AW + 2*AV_BW)*4)

__global__ __launch_bounds__(256, 2) void av_mma(
    float* __restrict__ P, const uint32_t* __restrict__ Vt,
    const float* __restrict__ gmx, const float* __restrict__ grs,
    uint32_t* __restrict__ AOp)
{
    extern __shared__ uint32_t sm[];
    const uint32_t sb = (uint32_t)__cvta_generic_to_shared(sm);
    const int tid = threadIdx.x, w = tid >> 5, l = tid & 31;
    const int z = blockIdx.y, b = z >> 4, h = z & 15;
    const int m0 = blockIdx.x << 7;
    const int wm = w << 4;
    float* Pz = P + (size_t)z * SS * SS;
    const uint32_t* Vz = Vt + (size_t)z * HDim * SS;

    // per-thread row stats (rows (tid>>4) + 16*i)
    float M[8], R[8];
    #pragma unroll
    for (int i = 0; i < 8; i++) {
        const int row = (tid >> 4) + 16 * i;
        M[i] = gmx[(size_t)z * SS + m0 + row];
        R[i] = grs[(size_t)z * SS + m0 + row];
    }

    auto stageB = [&](int c) {
        const uint32_t bB = sb + (AV_AW + (c & 1) * AV_BW) * 4;
        #pragma unroll
        for (int i = 0; i < 4; i++) {
            int g = tid + (i << 8), row = g >> 4, q = g & 15;
            cpa16(bB + (uint32_t)(row * 72 + q * 4) * 4,
                  Vz + (size_t)row * SS + c * 64 + q * 4);
        }
        CP_COMMIT();
    };
    stageB(0); stageB(1);

    float acc[8][4] = {};
    for (int c = 0; c < 32; c++) {
        // load raw P, normalize, write back, keep for packing
        float4 av[8];
        #pragma unroll
        for (int i = 0; i < 8; i++) {
            int g = tid + (i << 8), row = g >> 4, q = g & 15;
            float4 v = *(const float4*)(Pz + (size_t)(m0 + row) * SS + c * 64 + q * 4);
            v.x = __expf(v.x - M[i]) * R[i];
            v.y = __expf(v.y - M[i]) * R[i];
            v.z = __expf(v.z - M[i]) * R[i];
            v.w = __expf(v.w - M[i]) * R[i];
            *(float4*)(Pz + (size_t)(m0 + row) * SS + c * 64 + q * 4) = v;
            av[i] = v;
        }
        if (c < 31) CP_WAIT1(); else CP_WAIT0();
        __syncthreads();
        #pragma unroll
        for (int i = 0; i < 8; i++) {
            int g = tid + (i << 8), row = g >> 4, q = g & 15;
            sm[row * 72 + q * 4 + 0] = packf(av[i].x);
            sm[row * 72 + q * 4 + 1] = packf(av[i].y);
            sm[row * 72 + q * 4 + 2] = packf(av[i].z);
            sm[row * 72 + q * 4 + 3] = packf(av[i].w);
        }
        __syncthreads();
        const uint32_t* Bs = sm + AV_AW + (c & 1) * AV_BW;
        #pragma unroll
        for (int ks = 0; ks < 4; ks++) {
            uint32_t ah[4], al[4];
            lda_pk(sm, 72, wm, ks, l, ah, al);
            #pragma unroll
            for (int ni = 0; ni < 8; ni++) {
                uint32_t bh[2], bl[2];
                ldb_pk(Bs, 72, ni * 8, ks, l, bh, bl);
                mma_bf16(acc[ni], ah, bh);
                mma_bf16(acc[ni], ah, bl);
                mma_bf16(acc[ni], al, bh);
            }
        }
        __syncthreads();
        if (c + 2 < 32) stageB(c + 2);
    }

    #pragma unroll
    for (int ni = 0; ni < 8; ni++) {
        const int r = m0 + wm + (l >> 2);
        const int cc = ni * 8 + 2 * (l & 3);
        uint32_t* dst = AOp + ((size_t)b * SS + r) * DD + h * HDim + cc;
        *(uint2*)dst = make_uint2(packf(acc[ni][0]), packf(acc[ni][1]));
        *(uint2*)(dst + 8 * DD) = make_uint2(packf(acc[ni][2]), packf(acc[ni][3]));
    }
}

// ---------------------------------------------------------------------------
extern "C" void kernel_launch(void* const* d_in, const int* in_sizes, int n_in,
                              void* d_out, int out_size)
{
    const float* query = (const float*)d_in[0];
    const float* key_  = (const float*)d_in[1];
    const float* value = (const float*)d_in[2];
    const float* wq = (const float*)d_in[3];
    const float* bq = (const float*)d_in[4];
    const float* wk = (const float*)d_in[5];
    const float* bk = (const float*)d_in[6];
    const float* wv = (const float*)d_in[7];
    const float* bv = (const float*)d_in[8];
    const float* wo = (const float*)d_in[9];
    const float* bo = (const float*)d_in[10];

    float* out = (float*)d_out;                 // (B,S,D)
    float* attnw = out + (size_t)BB * SS * DD;  // (B,H,S,S)

    uint32_t *xq, *xk, *xv, *pwq, *pwk, *pwv, *pwo, *qp, *kp, *vt, *aop;
    float *mx, *rsum;
    cudaGetSymbolAddress((void**)&xq, g_xq);
    cudaGetSymbolAddress((void**)&xk, g_xk);
    cudaGetSymbolAddress((void**)&xv, g_xv);
    cudaGetSymbolAddress((void**)&pwq, g_wq);
    cudaGetSymbolAddress((void**)&pwk, g_wk);
    cudaGetSymbolAddress((void**)&pwv, g_wv);
    cudaGetSymbolAddress((void**)&pwo, g_wo);
    cudaGetSymbolAddress((void**)&qp, g_qp);
    cudaGetSymbolAddress((void**)&kp, g_kp);
    cudaGetSymbolAddress((void**)&vt, g_vt);
    cudaGetSymbolAddress((void**)&aop, g_aop);
    cudaGetSymbolAddress((void**)&mx, g_mx);
    cudaGetSymbolAddress((void**)&rsum, g_rs);

    cudaFuncSetAttribute(proj_mma<0>, cudaFuncAttributeMaxDynamicSharedMemorySize, PJ_SM);
    cudaFuncSetAttribute(proj_mma<1>, cudaFuncAttributeMaxDynamicSharedMemorySize, PJ_SM);
    cudaFuncSetAttribute(proj_mma<2>, cudaFuncAttributeMaxDynamicSharedMemorySize, PJ_SM);
    cudaFuncSetAttribute(scores_mma,  cudaFuncAttributeMaxDynamicSharedMemorySize, SC_SM);
    cudaFuncSetAttribute(av_mma,      cudaFuncAttributeMaxDynamicSharedMemorySize, AV_SM);

    const int nin4 = (BB * SS * DD) / 4;   // 1048576
    const int nw4  = (DD * DD) / 4;        // 262144
    pack3_kernel<<<dim3(nin4 / 256, 3), 256>>>(
        (const float4*)query, (const float4*)key_, (const float4*)value,
        (uint4*)xq, (uint4*)xk, (uint4*)xv, nin4);
    pack4_kernel<<<dim3(nw4 / 256, 4), 256>>>(
        (const float4*)wq, (const float4*)wk, (const float4*)wv, (const float4*)wo,
        (uint4*)pwq, (uint4*)pwk, (uint4*)pwv, (uint4*)pwo, nw4);

    const dim3 gproj(DD / 64, (BB * SS) / 128);   // (16, 32)
    proj_mma<0><<<gproj, 256, PJ_SM>>>(xq, pwq, bq, qp);
    proj_mma<0><<<gproj, 256, PJ_SM>>>(xk, pwk, bk, kp);
    proj_mma<1><<<gproj, 256, PJ_SM>>>(xv, pwv, bv, vt);

    scores_mma<<<dim3(SS / 64, NHZ), 256, SC_SM>>>(qp, kp, attnw, mx, rsum);

    av_mma<<<dim3(SS / 128, NHZ), 256, AV_SM>>>(attnw, vt, mx, rsum, aop);

    proj_mma<2><<<gproj, 256, PJ_SM>>>(aop, pwo, bo, out);
}

// round 7
// speedup vs baseline: 1.0200x; 1.0200x over previous
#include <cuda_runtime.h>
#include <cuda_bf16.h>
#include <cstdint>
#include <math.h>

#define BB 2
#define SS 2048
#define DD 1024
#define HH 16
#define HDim 64
#define NHZ (BB*HH)

// hi/lo bf16 planes (u32 = two adjacent bf16 of the same plane)
__device__ uint32_t g_xh[3][2097152], g_xl[3][2097152];      // packed inputs q,k,v
__device__ uint32_t g_wh[4][524288],  g_wl[4][524288];       // weights q,k,v,o
__device__ uint32_t g_qh[2097152], g_ql[2097152];            // Q (z,s,hd)
__device__ uint32_t g_kh[2097152], g_kl[2097152];            // K (z,s,hd)
__device__ uint32_t g_vh[2097152], g_vl[2097152];            // V transposed (z,hd,s)
__device__ uint32_t g_aoh[2097152], g_aol[2097152];          // attn out (b,s,d)

__device__ __forceinline__ void mma_bf16(float d[4], const uint32_t a[4], const uint32_t b[2]) {
    asm volatile(
        "mma.sync.aligned.m16n8k16.row.col.f32.bf16.bf16.f32 "
        "{%0,%1,%2,%3}, {%4,%5,%6,%7}, {%8,%9}, {%0,%1,%2,%3};"
        : "+f"(d[0]), "+f"(d[1]), "+f"(d[2]), "+f"(d[3])
        : "r"(a[0]), "r"(a[1]), "r"(a[2]), "r"(a[3]), "r"(b[0]), "r"(b[1]));
}
__device__ __forceinline__ void ldsm4(uint32_t addr, uint32_t r[4]) {
    asm volatile("ldmatrix.sync.aligned.m8n8.x4.shared.b16 {%0,%1,%2,%3}, [%4];"
                 : "=r"(r[0]), "=r"(r[1]), "=r"(r[2]), "=r"(r[3]) : "r"(addr));
}
__device__ __forceinline__ void split2(float a, float b, uint32_t& h, uint32_t& l) {
    __nv_bfloat16 ah = __float2bfloat16(a);
    __nv_bfloat16 bh = __float2bfloat16(b);
    __nv_bfloat16 al = __float2bfloat16(a - __bfloat162float(ah));
    __nv_bfloat16 bl = __float2bfloat16(b - __bfloat162float(bh));
    h = (uint32_t)__bfloat16_as_ushort(ah) | ((uint32_t)__bfloat16_as_ushort(bh) << 16);
    l = (uint32_t)__bfloat16_as_ushort(al) | ((uint32_t)__bfloat16_as_ushort(bl) << 16);
}
__device__ __forceinline__ void splits(float x, unsigned short& h, unsigned short& l) {
    __nv_bfloat16 bh = __float2bfloat16(x);
    h = __bfloat16_as_ushort(bh);
    l = __bfloat16_as_ushort(__float2bfloat16(x - __bfloat162float(bh)));
}
__device__ __forceinline__ void cpa16(uint32_t dst, const void* src) {
    asm volatile("cp.async.cg.shared.global [%0], [%1], 16;" :: "r"(dst), "l"(src));
}
#define CP_COMMIT() asm volatile("cp.async.commit_group;" ::: "memory")
#define CP_WAIT1() asm volatile("cp.async.wait_group 1;" ::: "memory")
#define CP_WAIT0() asm volatile("cp.async.wait_group 0;" ::: "memory")

// ---------------------------------------------------------------------------
// pack inputs / weights into planes
// ---------------------------------------------------------------------------
__global__ void pack_in(const float4* q, const float4* k, const float4* v,
                        uint2* qh, uint2* ql, uint2* kh, uint2* kl,
                        uint2* vh, uint2* vl, int n4) {
    int i = blockIdx.x * 256 + threadIdx.x;
    if (i >= n4) return;
    const float4* s = blockIdx.y == 0 ? q : blockIdx.y == 1 ? k : v;
    uint2* dh = blockIdx.y == 0 ? qh : blockIdx.y == 1 ? kh : vh;
    uint2* dl = blockIdx.y == 0 ? ql : blockIdx.y == 1 ? kl : vl;
    float4 x = s[i];
    uint32_t h0, l0, h1, l1;
    split2(x.x, x.y, h0, l0);
    split2(x.z, x.w, h1, l1);
    dh[i] = make_uint2(h0, h1);
    dl[i] = make_uint2(l0, l1);
}
__global__ void pack_w(const float4* a, const float4* b, const float4* c, const float4* d,
                       uint2* ah, uint2* al, uint2* bh, uint2* bl,
                       uint2* ch, uint2* cl, uint2* dh2, uint2* dl2, int n4) {
    int i = blockIdx.x * 256 + threadIdx.x;
    if (i >= n4) return;
    const float4* s = blockIdx.y == 0 ? a : blockIdx.y == 1 ? b : blockIdx.y == 2 ? c : d;
    uint2* oh = blockIdx.y == 0 ? ah : blockIdx.y == 1 ? bh : blockIdx.y == 2 ? ch : dh2;
    uint2* ol = blockIdx.y == 0 ? al : blockIdx.y == 1 ? bl : blockIdx.y == 2 ? cl : dl2;
    float4 x = s[i];
    uint32_t h0, l0, h1, l1;
    split2(x.x, x.y, h0, l0);
    split2(x.z, x.w, h1, l1);
    oh[i] = make_uint2(h0, h1);
    ol[i] = make_uint2(l0, l1);
}

// ---------------------------------------------------------------------------
// Projection: Y = X@W^T + bias. Tile 128x64, BK=32, 8 warps (4m x 2n).
// Plane smem row stride 20 u32 (16 data + 4 pad), conflict-free LDSM.
// MODE 0: planes (z,s,hd); MODE 1: planes transposed (z,hd,s); MODE 2: fp32.
// ---------------------------------------------------------------------------
#define PJ_AH(b) ((b)*2560)
#define PJ_AL(b) (5120 + (b)*2560)
#define PJ_BH(b) (10240 + (b)*1280)
#define PJ_BL(b) (12800 + (b)*1280)
#define PJ_SM (15360*4)

template <int MODE>
__global__ __launch_bounds__(256, 2) void proj_mma(
    const uint32_t* __restrict__ Xh, const uint32_t* __restrict__ Xl,
    const uint32_t* __restrict__ Wh, const uint32_t* __restrict__ Wl,
    const float* __restrict__ bias, void* __restrict__ Y0, void* __restrict__ Y1)
{
    extern __shared__ uint32_t sm[];
    const uint32_t sb = (uint32_t)__cvta_generic_to_shared(sm);
    const int tid = threadIdx.x, w = tid >> 5, l = tid & 31;
    const int m0 = blockIdx.y << 7, n0 = blockIdx.x << 6;
    const int wm = (w & 3) << 5, wn = (w >> 2) << 5;

    auto stage = [&](int c) {
        const int bi = c & 1;
        #pragma unroll
        for (int i = 0; i < 2; i++) {
            int g = tid + (i << 8), row = g >> 2, q = g & 3;
            const uint32_t so = (uint32_t)(row * 20 + q * 4) * 4;
            cpa16(sb + PJ_AH(bi) * 4 + so, Xh + (size_t)(m0 + row) * 512 + c * 16 + q * 4);
            cpa16(sb + PJ_AL(bi) * 4 + so, Xl + (size_t)(m0 + row) * 512 + c * 16 + q * 4);
        }
        {
            int row = tid >> 2, q = tid & 3;
            const uint32_t so = (uint32_t)(row * 20 + q * 4) * 4;
            cpa16(sb + PJ_BH(bi) * 4 + so, Wh + (size_t)(n0 + row) * 512 + c * 16 + q * 4);
            cpa16(sb + PJ_BL(bi) * 4 + so, Wl + (size_t)(n0 + row) * 512 + c * 16 + q * 4);
        }
        CP_COMMIT();
    };
    stage(0); stage(1);

    float acc[2][4][4] = {};
    for (int c = 0; c < 32; c++) {
        if (c < 31) CP_WAIT1(); else CP_WAIT0();
        __syncthreads();
        const int bi = c & 1;
        #pragma unroll
        for (int ks = 0; ks < 2; ks++) {
            const uint32_t ko = ks * 8 + (l >> 4) * 4;
            const uint32_t ra = (uint32_t)(l & 15);
            uint32_t ah0[4], ah1[4], al0[4], al1[4], b0h[4], b1h[4], b0l[4], b1l[4];
            ldsm4(sb + (PJ_AH(bi) + (wm + ra) * 20 + ko) * 4, ah0);
            ldsm4(sb + (PJ_AH(bi) + (wm + 16 + ra) * 20 + ko) * 4, ah1);
            ldsm4(sb + (PJ_AL(bi) + (wm + ra) * 20 + ko) * 4, al0);
            ldsm4(sb + (PJ_AL(bi) + (wm + 16 + ra) * 20 + ko) * 4, al1);
            ldsm4(sb + (PJ_BH(bi) + (wn + ra) * 20 + ko) * 4, b0h);
            ldsm4(sb + (PJ_BH(bi) + (wn + 16 + ra) * 20 + ko) * 4, b1h);
            ldsm4(sb + (PJ_BL(bi) + (wn + ra) * 20 + ko) * 4, b0l);
            ldsm4(sb + (PJ_BL(bi) + (wn + 16 + ra) * 20 + ko) * 4, b1l);
            #pragma unroll
            for (int ni = 0; ni < 4; ni++) {
                uint32_t bh[2], bl[2];
                if (ni == 0) { bh[0]=b0h[0]; bh[1]=b0h[2]; bl[0]=b0l[0]; bl[1]=b0l[2]; }
                if (ni == 1) { bh[0]=b0h[1]; bh[1]=b0h[3]; bl[0]=b0l[1]; bl[1]=b0l[3]; }
                if (ni == 2) { bh[0]=b1h[0]; bh[1]=b1h[2]; bl[0]=b1l[0]; bl[1]=b1l[2]; }
                if (ni == 3) { bh[0]=b1h[1]; bh[1]=b1h[3]; bl[0]=b1l[1]; bl[1]=b1l[3]; }
                mma_bf16(acc[0][ni], ah0, bh);
                mma_bf16(acc[0][ni], ah0, bl);
                mma_bf16(acc[0][ni], al0, bh);
                mma_bf16(acc[1][ni], ah1, bh);
                mma_bf16(acc[1][ni], ah1, bl);
                mma_bf16(acc[1][ni], al1, bh);
            }
        }
        __syncthreads();
        if (c + 2 < 32) stage(c + 2);
    }

    #pragma unroll
    for (int mi = 0; mi < 2; mi++) {
        #pragma unroll
        for (int ni = 0; ni < 4; ni++) {
            const int r = m0 + wm + mi * 16 + (l >> 2);
            const int cc = n0 + wn + ni * 8 + 2 * (l & 3);
            const float b0 = __ldg(bias + cc), b1 = __ldg(bias + cc + 1);
            float y00 = acc[mi][ni][0] + b0, y01 = acc[mi][ni][1] + b1;
            float y10 = acc[mi][ni][2] + b0, y11 = acc[mi][ni][3] + b1;
            if (MODE == 2) {
                float* O = (float*)Y0;
                *(float2*)(O + (size_t)r * DD + cc) = make_float2(y00, y01);
                *(float2*)(O + (size_t)(r + 8) * DD + cc) = make_float2(y10, y11);
            } else {
                const int bb = r >> 11, s = r & (SS - 1), h = cc >> 6, hd = cc & 63;
                if (MODE == 0) {
                    uint32_t* Yh = (uint32_t*)Y0;
                    uint32_t* Yl = (uint32_t*)Y1;
                    size_t zb = (size_t)(bb * HH + h) * SS;
                    uint32_t hh, ll;
                    split2(y00, y01, hh, ll);
                    Yh[(zb + s) * 32 + (hd >> 1)] = hh;
                    Yl[(zb + s) * 32 + (hd >> 1)] = ll;
                    split2(y10, y11, hh, ll);
                    Yh[(zb + s + 8) * 32 + (hd >> 1)] = hh;
                    Yl[(zb + s + 8) * 32 + (hd >> 1)] = ll;
                } else {
                    unsigned short* Yh = (unsigned short*)Y0;
                    unsigned short* Yl = (unsigned short*)Y1;
                    size_t zb = (size_t)(bb * HH + h) * HDim;
                    unsigned short hh, ll;
                    splits(y00, hh, ll);
                    Yh[(zb + hd) * SS + s] = hh;     Yl[(zb + hd) * SS + s] = ll;
                    splits(y01, hh, ll);
                    Yh[(zb + hd + 1) * SS + s] = hh; Yl[(zb + hd + 1) * SS + s] = ll;
                    splits(y10, hh, ll);
                    Yh[(zb + hd) * SS + s + 8] = hh; Yl[(zb + hd) * SS + s + 8] = ll;
                    splits(y11, hh, ll);
                    Yh[(zb + hd + 1) * SS + s + 8] = hh; Yl[(zb + hd + 1) * SS + s + 8] = ll;
                }
            }
        }
    }
}

// ---------------------------------------------------------------------------
// Scores: P = (Q K^T)*0.125 raw. CTA = 64-row strip x 16 n-tiles of 128.
// A resident (stride 36), B double-buffered. 8 warps (2m x 4n).
// ---------------------------------------------------------------------------
#define SC_AH 0
#define SC_AL 2304
#define SC_BH(b) (4608 + (b)*9216)
#define SC_BL(b) (4608 + (b)*9216 + 4608)
#define SC_SM (23040*4)

__global__ __launch_bounds__(256) void scores_mma(
    const uint32_t* __restrict__ Qh, const uint32_t* __restrict__ Ql,
    const uint32_t* __restrict__ Kh, const uint32_t* __restrict__ Kl,
    float* __restrict__ P)
{
    extern __shared__ uint32_t sm[];
    const uint32_t sb = (uint32_t)__cvta_generic_to_shared(sm);
    const int tid = threadIdx.x, w = tid >> 5, l = tid & 31;
    const int z = blockIdx.y, m0 = blockIdx.x << 6;
    const int wm = (w & 1) << 5, wn = (w >> 1) << 5;

    auto stageB = [&](int nt) {
        const int bi = nt & 1;
        #pragma unroll
        for (int i = 0; i < 4; i++) {
            int g = tid + (i << 8), row = g >> 3, q = g & 7;
            const uint32_t so = (uint32_t)(row * 36 + q * 4) * 4;
            cpa16(sb + SC_BH(bi) * 4 + so, Kh + ((size_t)z * SS + nt * 128 + row) * 32 + q * 4);
            cpa16(sb + SC_BL(bi) * 4 + so, Kl + ((size_t)z * SS + nt * 128 + row) * 32 + q * 4);
        }
    };
    #pragma unroll
    for (int i = 0; i < 2; i++) {
        int g = tid + (i << 8), row = g >> 3, q = g & 7;
        const uint32_t so = (uint32_t)(row * 36 + q * 4) * 4;
        cpa16(sb + SC_AH * 4 + so, Qh + ((size_t)z * SS + m0 + row) * 32 + q * 4);
        cpa16(sb + SC_AL * 4 + so, Ql + ((size_t)z * SS + m0 + row) * 32 + q * 4);
    }
    stageB(0); CP_COMMIT();
    stageB(1); CP_COMMIT();

    float* Pz = P + (size_t)z * SS * SS;
    for (int nt = 0; nt < 16; nt++) {
        if (nt < 15) CP_WAIT1(); else CP_WAIT0();
        __syncthreads();
        const int bi = nt & 1;
        float acc[2][4][4] = {};
        #pragma unroll
        for (int ks = 0; ks < 4; ks++) {
            const uint32_t ko = ks * 8 + (l >> 4) * 4;
            const uint32_t ra = (uint32_t)(l & 15);
            uint32_t ah0[4], ah1[4], al0[4], al1[4], b0h[4], b1h[4], b0l[4], b1l[4];
            ldsm4(sb + (SC_AH + (wm + ra) * 36 + ko) * 4, ah0);
            ldsm4(sb + (SC_AH + (wm + 16 + ra) * 36 + ko) * 4, ah1);
            ldsm4(sb + (SC_AL + (wm + ra) * 36 + ko) * 4, al0);
            ldsm4(sb + (SC_AL + (wm + 16 + ra) * 36 + ko) * 4, al1);
            ldsm4(sb + (SC_BH(bi) + (wn + ra) * 36 + ko) * 4, b0h);
            ldsm4(sb + (SC_BH(bi) + (wn + 16 + ra) * 36 + ko) * 4, b1h);
            ldsm4(sb + (SC_BL(bi) + (wn + ra) * 36 + ko) * 4, b0l);
            ldsm4(sb + (SC_BL(bi) + (wn + 16 + ra) * 36 + ko) * 4, b1l);
            #pragma unroll
            for (int ni = 0; ni < 4; ni++) {
                uint32_t bh[2], bl[2];
                if (ni == 0) { bh[0]=b0h[0]; bh[1]=b0h[2]; bl[0]=b0l[0]; bl[1]=b0l[2]; }
                if (ni == 1) { bh[0]=b0h[1]; bh[1]=b0h[3]; bl[0]=b0l[1]; bl[1]=b0l[3]; }
                if (ni == 2) { bh[0]=b1h[0]; bh[1]=b1h[2]; bl[0]=b1l[0]; bl[1]=b1l[2]; }
                if (ni == 3) { bh[0]=b1h[1]; bh[1]=b1h[3]; bl[0]=b1l[1]; bl[1]=b1l[3]; }
                mma_bf16(acc[0][ni], ah0, bh);
                mma_bf16(acc[0][ni], ah0, bl);
                mma_bf16(acc[0][ni], al0, bh);
                mma_bf16(acc[1][ni], ah1, bh);
                mma_bf16(acc[1][ni], ah1, bl);
                mma_bf16(acc[1][ni], al1, bh);
            }
        }
        __syncthreads();
        if (nt + 2 < 16) { stageB(nt + 2); CP_COMMIT(); }
        #pragma unroll
        for (int mi = 0; mi < 2; mi++) {
            #pragma unroll
            for (int ni = 0; ni < 4; ni++) {
                const int r = m0 + wm + mi * 16 + (l >> 2);
                const int cc = nt * 128 + wn + ni * 8 + 2 * (l & 3);
                *(float2*)(Pz + (size_t)r * SS + cc) =
                    make_float2(acc[mi][ni][0] * 0.125f, acc[mi][ni][1] * 0.125f);
                *(float2*)(Pz + (size_t)(r + 8) * SS + cc) =
                    make_float2(acc[mi][ni][2] * 0.125f, acc[mi][ni][3] * 0.125f);
            }
        }
    }
}

// ---------------------------------------------------------------------------
// Row softmax in-place (fp32 P), one block per 2048-row.
// ---------------------------------------------------------------------------
__global__ __launch_bounds__(256) void softmax_kernel(float* __restrict__ P)
{
    const size_t row = blockIdx.x;
    float4* p = (float4*)(P + row * (size_t)SS);
    const int t = threadIdx.x;
    float4 a = p[t];
    float4 b = p[t + 256];
    float mx = fmaxf(fmaxf(fmaxf(a.x, a.y), fmaxf(a.z, a.w)),
                     fmaxf(fmaxf(b.x, b.y), fmaxf(b.z, b.w)));
    #pragma unroll
    for (int o = 16; o > 0; o >>= 1) mx = fmaxf(mx, __shfl_xor_sync(0xFFFFFFFFu, mx, o));
    __shared__ float rmax[8], rsum[8];
    if ((t & 31) == 0) rmax[t >> 5] = mx;
    __syncthreads();
    mx = fmaxf(fmaxf(fmaxf(rmax[0], rmax[1]), fmaxf(rmax[2], rmax[3])),
               fmaxf(fmaxf(rmax[4], rmax[5]), fmaxf(rmax[6], rmax[7])));
    a.x = __expf(a.x - mx); a.y = __expf(a.y - mx);
    a.z = __expf(a.z - mx); a.w = __expf(a.w - mx);
    b.x = __expf(b.x - mx); b.y = __expf(b.y - mx);
    b.z = __expf(b.z - mx); b.w = __expf(b.w - mx);
    float s = a.x + a.y + a.z + a.w + b.x + b.y + b.z + b.w;
    #pragma unroll
    for (int o = 16; o > 0; o >>= 1) s += __shfl_xor_sync(0xFFFFFFFFu, s, o);
    if ((t & 31) == 0) rsum[t >> 5] = s;
    __syncthreads();
    s = rsum[0] + rsum[1] + rsum[2] + rsum[3] + rsum[4] + rsum[5] + rsum[6] + rsum[7];
    const float inv = 1.0f / s;
    a.x *= inv; a.y *= inv; a.z *= inv; a.w *= inv;
    b.x *= inv; b.y *= inv; b.z *= inv; b.w *= inv;
    p[t] = a;
    p[t + 256] = b;
}

// ---------------------------------------------------------------------------
// AV: AO = P @ V. Tile 128x64, BK=64 (32 chunks). A: fp32 P converted to
// planes in smem; B: V^T planes via cp.async. 8 warps, warp 16x64.
// ---------------------------------------------------------------------------
#define AV_AH 0
#define AV_AL 4608
#define AV_BH(b) (9216 + (b)*4608)
#define AV_BL(b) (9216 + (b)*4608 + 2304)
#define AV_SM (18432*4)

__global__ __launch_bounds__(256, 2) void av_mma(
    const float* __restrict__ P, const uint32_t* __restrict__ Vh,
    const uint32_t* __restrict__ Vl,
    uint32_t* __restrict__ AOh, uint32_t* __restrict__ AOl)
{
    extern __shared__ uint32_t sm[];
    const uint32_t sb = (uint32_t)__cvta_generic_to_shared(sm);
    const int tid = threadIdx.x, w = tid >> 5, l = tid & 31;
    const int z = blockIdx.y, bb = z >> 4, h = z & 15;
    const int m0 = blockIdx.x << 7;
    const int wm = w << 4;
    const float* Pz = P + (size_t)z * SS * SS;

    auto stageB = [&](int c) {
        const int bi = c & 1;
        #pragma unroll
        for (int i = 0; i < 2; i++) {
            int g = tid + (i << 8), row = g >> 3, q = g & 7;
            const uint32_t so = (uint32_t)(row * 36 + q * 4) * 4;
            cpa16(sb + AV_BH(bi) * 4 + so, Vh + ((size_t)z * HDim + row) * 1024 + c * 32 + q * 4);
            cpa16(sb + AV_BL(bi) * 4 + so, Vl + ((size_t)z * HDim + row) * 1024 + c * 32 + q * 4);
        }
        CP_COMMIT();
    };
    stageB(0); stageB(1);

    float acc[8][4] = {};
    for (int c = 0; c < 32; c++) {
        float4 av[8];
        #pragma unroll
        for (int i = 0; i < 8; i++) {
            int g = tid + (i << 8), row = g >> 4, q = g & 15;
            av[i] = *(const float4*)(Pz + (size_t)(m0 + row) * SS + c * 64 + q * 4);
        }
        if (c < 31) CP_WAIT1(); else CP_WAIT0();
        __syncthreads();
        #pragma unroll
        for (int i = 0; i < 8; i++) {
            int g = tid + (i << 8), row = g >> 4, q = g & 15;
            uint32_t h0, l0, h1, l1;
            split2(av[i].x, av[i].y, h0, l0);
            split2(av[i].z, av[i].w, h1, l1);
            sm[AV_AH + row * 36 + 2 * q]     = h0;
            sm[AV_AH + row * 36 + 2 * q + 1] = h1;
            sm[AV_AL + row * 36 + 2 * q]     = l0;
            sm[AV_AL + row * 36 + 2 * q + 1] = l1;
        }
        __syncthreads();
        const int bi = c & 1;
        #pragma unroll
        for (int ks = 0; ks < 4; ks++) {
            const uint32_t ko = ks * 8 + (l >> 4) * 4;
            const uint32_t ra = (uint32_t)(l & 15);
            uint32_t ah[4], al[4];
            ldsm4(sb + (AV_AH + (wm + ra) * 36 + ko) * 4, ah);
            ldsm4(sb + (AV_AL + (wm + ra) * 36 + ko) * 4, al);
            #pragma unroll
            for (int j = 0; j < 4; j++) {
                uint32_t bhm[4], blm[4];
                ldsm4(sb + (AV_BH(bi) + (j * 16 + ra) * 36 + ko) * 4, bhm);
                ldsm4(sb + (AV_BL(bi) + (j * 16 + ra) * 36 + ko) * 4, blm);
                uint32_t bh[2], bl[2];
                bh[0] = bhm[0]; bh[1] = bhm[2]; bl[0] = blm[0]; bl[1] = blm[2];
                mma_bf16(acc[2 * j], ah, bh);
                mma_bf16(acc[2 * j], ah, bl);
                mma_bf16(acc[2 * j], al, bh);
                bh[0] = bhm[1]; bh[1] = bhm[3]; bl[0] = blm[1]; bl[1] = blm[3];
                mma_bf16(acc[2 * j + 1], ah, bh);
                mma_bf16(acc[2 * j + 1], ah, bl);
                mma_bf16(acc[2 * j + 1], al, bh);
            }
        }
        __syncthreads();
        if (c + 2 < 32) stageB(c + 2);
    }

    #pragma unroll
    for (int ni = 0; ni < 8; ni++) {
        const int r = m0 + wm + (l >> 2);
        const int cc = ni * 8 + 2 * (l & 3);
        uint32_t hh, ll;
        split2(acc[ni][0], acc[ni][1], hh, ll);
        AOh[((size_t)bb * SS + r) * 512 + (h * 64 + cc) / 2] = hh;
        AOl[((size_t)bb * SS + r) * 512 + (h * 64 + cc) / 2] = ll;
        split2(acc[ni][2], acc[ni][3], hh, ll);
        AOh[((size_t)bb * SS + r + 8) * 512 + (h * 64 + cc) / 2] = hh;
        AOl[((size_t)bb * SS + r + 8) * 512 + (h * 64 + cc) / 2] = ll;
    }
}

// ---------------------------------------------------------------------------
extern "C" void kernel_launch(void* const* d_in, const int* in_sizes, int n_in,
                              void* d_out, int out_size)
{
    const float* query = (const float*)d_in[0];
    const float* key_  = (const float*)d_in[1];
    const float* value = (const float*)d_in[2];
    const float* wq = (const float*)d_in[3];
    const float* bq = (const float*)d_in[4];
    const float* wk = (const float*)d_in[5];
    const float* bk = (const float*)d_in[6];
    const float* wv = (const float*)d_in[7];
    const float* bv = (const float*)d_in[8];
    const float* wo = (const float*)d_in[9];
    const float* bo = (const float*)d_in[10];

    float* out = (float*)d_out;                 // (B,S,D)
    float* attnw = out + (size_t)BB * SS * DD;  // (B,H,S,S)

    uint32_t *xh, *xl, *wh, *wl, *qh, *ql, *kh, *kl, *vh, *vl, *aoh, *aol;
    cudaGetSymbolAddress((void**)&xh, g_xh);
    cudaGetSymbolAddress((void**)&xl, g_xl);
    cudaGetSymbolAddress((void**)&wh, g_wh);
    cudaGetSymbolAddress((void**)&wl, g_wl);
    cudaGetSymbolAddress((void**)&qh, g_qh);
    cudaGetSymbolAddress((void**)&ql, g_ql);
    cudaGetSymbolAddress((void**)&kh, g_kh);
    cudaGetSymbolAddress((void**)&kl, g_kl);
    cudaGetSymbolAddress((void**)&vh, g_vh);
    cudaGetSymbolAddress((void**)&vl, g_vl);
    cudaGetSymbolAddress((void**)&aoh, g_aoh);
    cudaGetSymbolAddress((void**)&aol, g_aol);

    cudaFuncSetAttribute(proj_mma<0>, cudaFuncAttributeMaxDynamicSharedMemorySize, PJ_SM);
    cudaFuncSetAttribute(proj_mma<1>, cudaFuncAttributeMaxDynamicSharedMemorySize, PJ_SM);
    cudaFuncSetAttribute(proj_mma<2>, cudaFuncAttributeMaxDynamicSharedMemorySize, PJ_SM);
    cudaFuncSetAttribute(scores_mma,  cudaFuncAttributeMaxDynamicSharedMemorySize, SC_SM);
    cudaFuncSetAttribute(av_mma,      cudaFuncAttributeMaxDynamicSharedMemorySize, AV_SM);

    const int nin4 = (BB * SS * DD) / 4;   // 1048576
    const int nw4  = (DD * DD) / 4;        // 262144
    const size_t IN_PL = 2097152, W_PL = 524288;
    pack_in<<<dim3(nin4 / 256, 3), 256>>>(
        (const float4*)query, (const float4*)key_, (const float4*)value,
        (uint2*)(xh + 0 * IN_PL), (uint2*)(xl + 0 * IN_PL),
        (uint2*)(xh + 1 * IN_PL), (uint2*)(xl + 1 * IN_PL),
        (uint2*)(xh + 2 * IN_PL), (uint2*)(xl + 2 * IN_PL), nin4);
    pack_w<<<dim3(nw4 / 256, 4), 256>>>(
        (const float4*)wq, (const float4*)wk, (const float4*)wv, (const float4*)wo,
        (uint2*)(wh + 0 * W_PL), (uint2*)(wl + 0 * W_PL),
        (uint2*)(wh + 1 * W_PL), (uint2*)(wl + 1 * W_PL),
        (uint2*)(wh + 2 * W_PL), (uint2*)(wl + 2 * W_PL),
        (uint2*)(wh + 3 * W_PL), (uint2*)(wl + 3 * W_PL), nw4);

    const dim3 gproj(DD / 64, (BB * SS) / 128);   // (16, 32)
    proj_mma<0><<<gproj, 256, PJ_SM>>>(xh + 0 * IN_PL, xl + 0 * IN_PL,
                                       wh + 0 * W_PL, wl + 0 * W_PL, bq, qh, ql);
    proj_mma<0><<<gproj, 256, PJ_SM>>>(xh + 1 * IN_PL, xl + 1 * IN_PL,
                                       wh + 1 * W_PL, wl + 1 * W_PL, bk, kh, kl);
    proj_mma<1><<<gproj, 256, PJ_SM>>>(xh + 2 * IN_PL, xl + 2 * IN_PL,
                                       wh + 2 * W_PL, wl + 2 * W_PL, bv, vh, vl);

    scores_mma<<<dim3(SS / 64, NHZ), 256, SC_SM>>>(qh, ql, kh, kl, attnw);

    softmax_kernel<<<NHZ * SS, 256>>>(attnw);

    av_mma<<<dim3(SS / 128, NHZ), 256, AV_SM>>>(attnw, vh, vl, aoh, aol);

    proj_mma<2><<<gproj, 256, PJ_SM>>>(aoh, aol, wh + 3 * W_PL, wl + 3 * W_PL,
                                       bo, out, nullptr);
}

// round 8
// speedup vs baseline: 1.2013x; 1.1777x over previous
#include <cuda_runtime.h>
#include <cuda_bf16.h>
#include <cstdint>
#include <math.h>

#define BB 2
#define SS 2048
#define DD 1024
#define HH 16
#define HDim 64
#define NHZ (BB*HH)

// Packed scratch: u32 = bf16_hi | bf16_lo<<16
__device__ uint32_t g_xq[4194304], g_xk[4194304], g_xv[4194304];
__device__ uint32_t g_wq[1048576], g_wk[1048576], g_wv[1048576], g_wo[1048576];
__device__ uint32_t g_qp[4194304];   // Q packed (z,s,hd)
__device__ uint32_t g_kp[4194304];   // K packed (z,s,hd)
__device__ uint32_t g_vt[4194304];   // V packed transposed (z,hd,s)
__device__ uint32_t g_aop[4194304];  // attn_output packed (b,s,d)

__device__ __forceinline__ void mma_bf16(float d[4], const uint32_t a[4], const uint32_t b[2]) {
    asm volatile(
        "mma.sync.aligned.m16n8k16.row.col.f32.bf16.bf16.f32 "
        "{%0,%1,%2,%3}, {%4,%5,%6,%7}, {%8,%9}, {%0,%1,%2,%3};"
        : "+f"(d[0]), "+f"(d[1]), "+f"(d[2]), "+f"(d[3])
        : "r"(a[0]), "r"(a[1]), "r"(a[2]), "r"(a[3]), "r"(b[0]), "r"(b[1]));
}
__device__ __forceinline__ uint32_t packf(float x) {
    __nv_bfloat16 h = __float2bfloat16(x);
    __nv_bfloat16 l = __float2bfloat16(x - __bfloat162float(h));
    return (uint32_t)__bfloat16_as_ushort(h) | ((uint32_t)__bfloat16_as_ushort(l) << 16);
}
__device__ __forceinline__ void cpa16(uint32_t dst, const void* src) {
    asm volatile("cp.async.cg.shared.global [%0], [%1], 16;" :: "r"(dst), "l"(src));
}
#define CP_COMMIT() asm volatile("cp.async.commit_group;" ::: "memory")
#define CP_WAIT1() asm volatile("cp.async.wait_group 1;" ::: "memory")
#define CP_WAIT0() asm volatile("cp.async.wait_group 0;" ::: "memory")

// Fragment loads from packed smem; 1 PRMT per output register.
__device__ __forceinline__ void lda_pk(const uint32_t* S, int lda, int r, int ks, int l,
                                       uint32_t ah[4], uint32_t al[4]) {
    const uint32_t* p = S + (r + (l >> 2)) * lda + ks * 16 + 2 * (l & 3);
    uint2 q0 = *(const uint2*)p;
    uint2 q1 = *(const uint2*)(p + 8);
    uint2 q2 = *(const uint2*)(p + 8 * lda);
    uint2 q3 = *(const uint2*)(p + 8 * lda + 8);
    ah[0] = __byte_perm(q0.x, q0.y, 0x5410); al[0] = __byte_perm(q0.x, q0.y, 0x7632);
    ah[1] = __byte_perm(q2.x, q2.y, 0x5410); al[1] = __byte_perm(q2.x, q2.y, 0x7632);
    ah[2] = __byte_perm(q1.x, q1.y, 0x5410); al[2] = __byte_perm(q1.x, q1.y, 0x7632);
    ah[3] = __byte_perm(q3.x, q3.y, 0x5410); al[3] = __byte_perm(q3.x, q3.y, 0x7632);
}
__device__ __forceinline__ void ldb_pk(const uint32_t* S, int lda, int n, int ks, int l,
                                       uint32_t bh[2], uint32_t bl[2]) {
    const uint32_t* p = S + (n + (l >> 2)) * lda + ks * 16 + 2 * (l & 3);
    uint2 q0 = *(const uint2*)p;
    uint2 q1 = *(const uint2*)(p + 8);
    bh[0] = __byte_perm(q0.x, q0.y, 0x5410); bl[0] = __byte_perm(q0.x, q0.y, 0x7632);
    bh[1] = __byte_perm(q1.x, q1.y, 0x5410); bl[1] = __byte_perm(q1.x, q1.y, 0x7632);
}

// Batched packs: blockIdx.y selects the array.
__global__ void pack3_kernel(const float4* s0, const float4* s1, const float4* s2,
                             uint4* d0, uint4* d1, uint4* d2, int n4) {
    int i = blockIdx.x * 256 + threadIdx.x;
    const float4* s = (blockIdx.y == 0) ? s0 : (blockIdx.y == 1) ? s1 : s2;
    uint4* d = (blockIdx.y == 0) ? d0 : (blockIdx.y == 1) ? d1 : d2;
    if (i < n4) {
        float4 v = s[i];
        d[i] = make_uint4(packf(v.x), packf(v.y), packf(v.z), packf(v.w));
    }
}
__global__ void pack4_kernel(const float4* s0, const float4* s1, const float4* s2, const float4* s3,
                             uint4* d0, uint4* d1, uint4* d2, uint4* d3, int n4) {
    int i = blockIdx.x * 256 + threadIdx.x;
    const float4* s = (blockIdx.y == 0) ? s0 : (blockIdx.y == 1) ? s1
                    : (blockIdx.y == 2) ? s2 : s3;
    uint4* d = (blockIdx.y == 0) ? d0 : (blockIdx.y == 1) ? d1
             : (blockIdx.y == 2) ? d2 : d3;
    if (i < n4) {
        float4 v = s[i];
        d[i] = make_uint4(packf(v.x), packf(v.y), packf(v.z), packf(v.w));
    }
}

// ---------------------------------------------------------------------------
// Projection: Y = X@W^T + bias. Tile 128x64, BK=32, 8 warps (4m x 2n).
// blockIdx.z selects (X, W, bias, Y, mode). mode 0: packed (z,s,hd);
// mode 1: packed transposed (z,hd,s); mode 2: fp32 row-major.
// ---------------------------------------------------------------------------
#define PJ_AW (128*40)
#define PJ_BW (64*40)
#define PJ_SM ((2*PJ_AW + 2*PJ_BW)*4)

struct PJArgs {
    const uint32_t* X[3];
    const uint32_t* W[3];
    const float*    Bs[3];
    void*           Y[3];
    int             mode[3];
};

__global__ __launch_bounds__(256, 2) void proj_mma(PJArgs a)
{
    extern __shared__ uint32_t sm[];
    const uint32_t sb = (uint32_t)__cvta_generic_to_shared(sm);
    const int zi = blockIdx.z;
    const uint32_t* __restrict__ Xp = a.X[zi];
    const uint32_t* __restrict__ Wp = a.W[zi];
    const float* __restrict__ bias = a.Bs[zi];
    void* __restrict__ Yv = a.Y[zi];
    const int MODE = a.mode[zi];

    const int tid = threadIdx.x, w = tid >> 5, l = tid & 31;
    const int m0 = blockIdx.y << 7, n0 = blockIdx.x << 6;
    const int wm = (w & 3) << 5, wn = (w >> 2) << 5;

    auto stage = [&](int c) {
        const int bi = c & 1;
        const uint32_t aB = sb + bi * (PJ_AW * 4);
        #pragma unroll
        for (int i = 0; i < 4; i++) {
            int g = tid + (i << 8), row = g >> 3, q = g & 7;
            cpa16(aB + (uint32_t)(row * 40 + q * 4) * 4,
                  Xp + (size_t)(m0 + row) * DD + c * 32 + q * 4);
        }
        const uint32_t bB = sb + (2 * PJ_AW + bi * PJ_BW) * 4;
        #pragma unroll
        for (int i = 0; i < 2; i++) {
            int g = tid + (i << 8), row = g >> 3, q = g & 7;
            cpa16(bB + (uint32_t)(row * 40 + q * 4) * 4,
                  Wp + (size_t)(n0 + row) * DD + c * 32 + q * 4);
        }
        CP_COMMIT();
    };
    stage(0); stage(1);

    float acc[2][4][4] = {};
    for (int c = 0; c < 32; c++) {
        if (c < 31) CP_WAIT1(); else CP_WAIT0();
        __syncthreads();
        const uint32_t* As = sm + (c & 1) * PJ_AW;
        const uint32_t* Bs = sm + 2 * PJ_AW + (c & 1) * PJ_BW;
        #pragma unroll
        for (int ks = 0; ks < 2; ks++) {
            uint32_t ah[2][4], al[2][4];
            lda_pk(As, 40, wm, ks, l, ah[0], al[0]);
            lda_pk(As, 40, wm + 16, ks, l, ah[1], al[1]);
            #pragma unroll
            for (int ni = 0; ni < 4; ni++) {
                uint32_t bh[2], bl[2];
                ldb_pk(Bs, 40, wn + ni * 8, ks, l, bh, bl);
                #pragma unroll
                for (int mi = 0; mi < 2; mi++) {
                    mma_bf16(acc[mi][ni], ah[mi], bh);
                    mma_bf16(acc[mi][ni], ah[mi], bl);
                    mma_bf16(acc[mi][ni], al[mi], bh);
                }
            }
        }
        __syncthreads();
        if (c + 2 < 32) stage(c + 2);
    }

    #pragma unroll
    for (int mi = 0; mi < 2; mi++) {
        #pragma unroll
        for (int ni = 0; ni < 4; ni++) {
            const int r = m0 + wm + mi * 16 + (l >> 2);
            const int cc = n0 + wn + ni * 8 + 2 * (l & 3);
            const float b0 = __ldg(bias + cc), b1 = __ldg(bias + cc + 1);
            float y00 = acc[mi][ni][0] + b0, y01 = acc[mi][ni][1] + b1;
            float y10 = acc[mi][ni][2] + b0, y11 = acc[mi][ni][3] + b1;
            if (MODE == 2) {
                float* O = (float*)Yv;
                *(float2*)(O + (size_t)r * DD + cc) = make_float2(y00, y01);
                *(float2*)(O + (size_t)(r + 8) * DD + cc) = make_float2(y10, y11);
            } else {
                uint32_t* Y = (uint32_t*)Yv;
                const int b_ = r >> 11, s = r & (SS - 1), h = cc >> 6, hd = cc & 63;
                if (MODE == 0) {
                    size_t zb = (size_t)(b_ * HH + h) * SS;
                    *(uint2*)(Y + (zb + s) * HDim + hd) = make_uint2(packf(y00), packf(y01));
                    *(uint2*)(Y + (zb + s + 8) * HDim + hd) = make_uint2(packf(y10), packf(y11));
                } else {
                    size_t zb = (size_t)(b_ * HH + h) * HDim;
                    Y[(zb + hd) * SS + s]         = packf(y00);
                    Y[(zb + hd + 1) * SS + s]     = packf(y01);
                    Y[(zb + hd) * SS + s + 8]     = packf(y10);
                    Y[(zb + hd + 1) * SS + s + 8] = packf(y11);
                }
            }
        }
    }
}

// ---------------------------------------------------------------------------
// Scores: P = (Q K^T)*0.125. CTA = 64-row strip, loops 16 n-tiles of 128.
// A (64x64 words) resident; B double-buffered. 8 warps (2m x 4n), warp 32x32.
// ---------------------------------------------------------------------------
#define SC_AW (64*72)
#define SC_BW (128*72)
#define SC_SM ((SC_AW + 2*SC_BW)*4)

__global__ __launch_bounds__(256) void scores_mma(
    const uint32_t* __restrict__ Qp, const uint32_t* __restrict__ Kp,
    float* __restrict__ P)
{
    extern __shared__ uint32_t sm[];
    const uint32_t sb = (uint32_t)__cvta_generic_to_shared(sm);
    const int tid = threadIdx.x, w = tid >> 5, l = tid & 31;
    const int z = blockIdx.y, m0 = blockIdx.x << 6;
    const int wm = (w & 1) << 5, wn = (w >> 1) << 5;

    auto stageB = [&](int nt) {
        const uint32_t bB = sb + (SC_AW + (nt & 1) * SC_BW) * 4;
        #pragma unroll
        for (int i = 0; i < 8; i++) {
            int g = tid + (i << 8), row = g >> 4, q = g & 15;
            cpa16(bB + (uint32_t)(row * 72 + q * 4) * 4,
                  Kp + ((size_t)z * SS + nt * 128 + row) * HDim + q * 4);
        }
    };
    #pragma unroll
    for (int i = 0; i < 4; i++) {
        int g = tid + (i << 8), row = g >> 4, q = g & 15;
        cpa16(sb + (uint32_t)(row * 72 + q * 4) * 4,
              Qp + ((size_t)z * SS + m0 + row) * HDim + q * 4);
    }
    stageB(0); CP_COMMIT();
    stageB(1); CP_COMMIT();

    float* Pz = P + (size_t)z * SS * SS;
    for (int nt = 0; nt < 16; nt++) {
        if (nt < 15) CP_WAIT1(); else CP_WAIT0();
        __syncthreads();
        const uint32_t* Bs = sm + SC_AW + (nt & 1) * SC_BW;
        float acc[2][4][4] = {};
        #pragma unroll
        for (int ks = 0; ks < 4; ks++) {
            uint32_t ah[2][4], al[2][4];
            lda_pk(sm, 72, wm, ks, l, ah[0], al[0]);
            lda_pk(sm, 72, wm + 16, ks, l, ah[1], al[1]);
            #pragma unroll
            for (int ni = 0; ni < 4; ni++) {
                uint32_t bh[2], bl[2];
                ldb_pk(Bs, 72, wn + ni * 8, ks, l, bh, bl);
                #pragma unroll
                for (int mi = 0; mi < 2; mi++) {
                    mma_bf16(acc[mi][ni], ah[mi], bh);
                    mma_bf16(acc[mi][ni], ah[mi], bl);
                    mma_bf16(acc[mi][ni], al[mi], bh);
                }
            }
        }
        __syncthreads();
        if (nt + 2 < 16) { stageB(nt + 2); CP_COMMIT(); }
        #pragma unroll
        for (int mi = 0; mi < 2; mi++) {
            #pragma unroll
            for (int ni = 0; ni < 4; ni++) {
                const int r = m0 + wm + mi * 16 + (l >> 2);
                const int cc = nt * 128 + wn + ni * 8 + 2 * (l & 3);
                *(float2*)(Pz + (size_t)r * SS + cc) =
                    make_float2(acc[mi][ni][0] * 0.125f, acc[mi][ni][1] * 0.125f);
                *(float2*)(Pz + (size_t)(r + 8) * SS + cc) =
                    make_float2(acc[mi][ni][2] * 0.125f, acc[mi][ni][3] * 0.125f);
            }
        }
    }
}

// ---------------------------------------------------------------------------
// AV: AO = P @ V. Tile 128x64, BK=64 (32 chunks). A converted fp32->packed
// in-kernel (register-prefetched); B (V transposed, packed) cp.async.
// 8 warps, warp 16x64. Writes packed AO.
// ---------------------------------------------------------------------------
#define AV_AW (128*72)
#define AV_BW (64*72)
#define AV_SM ((AV_AW + 2*AV_BW)*4)

__global__ __launch_bounds__(256, 2) void av_mma(
    const float* __restrict__ P, const uint32_t* __restrict__ Vt,
    uint32_t* __restrict__ AOp)
{
    extern __shared__ uint32_t sm[];
    const uint32_t sb = (uint32_t)__cvta_generic_to_shared(sm);
    const int tid = threadIdx.x, w = tid >> 5, l = tid & 31;
    const int z = blockIdx.y, b = z >> 4, h = z & 15;
    const int m0 = blockIdx.x << 7;
    const int wm = w << 4;
    const float* Pz = P + (size_t)z * SS * SS;
    const uint32_t* Vz = Vt + (size_t)z * HDim * SS;

    auto stageB = [&](int c) {
        const uint32_t bB = sb + (AV_AW + (c & 1) * AV_BW) * 4;
        #pragma unroll
        for (int i = 0; i < 4; i++) {
            int g = tid + (i << 8), row = g >> 4, q = g & 15;
            cpa16(bB + (uint32_t)(row * 72 + q * 4) * 4,
                  Vz + (size_t)row * SS + c * 64 + q * 4);
        }
        CP_COMMIT();
    };
    stageB(0); stageB(1);

    float acc[8][4] = {};
    for (int c = 0; c < 32; c++) {
        float4 av[8];
        #pragma unroll
        for (int i = 0; i < 8; i++) {
            int g = tid + (i << 8), row = g >> 4, q = g & 15;
            av[i] = *(const float4*)(Pz + (size_t)(m0 + row) * SS + c * 64 + q * 4);
        }
        if (c < 31) CP_WAIT1(); else CP_WAIT0();
        __syncthreads();
        #pragma unroll
        for (int i = 0; i < 8; i++) {
            int g = tid + (i << 8), row = g >> 4, q = g & 15;
            sm[row * 72 + q * 4 + 0] = packf(av[i].x);
            sm[row * 72 + q * 4 + 1] = packf(av[i].y);
            sm[row * 72 + q * 4 + 2] = packf(av[i].z);
            sm[row * 72 + q * 4 + 3] = packf(av[i].w);
        }
        __syncthreads();
        const uint32_t* Bs = sm + AV_AW + (c & 1) * AV_BW;
        #pragma unroll
        for (int ks = 0; ks < 4; ks++) {
            uint32_t ah[4], al[4];
            lda_pk(sm, 72, wm, ks, l, ah, al);
            #pragma unroll
            for (int ni = 0; ni < 8; ni++) {
                uint32_t bh[2], bl[2];
                ldb_pk(Bs, 72, ni * 8, ks, l, bh, bl);
                mma_bf16(acc[ni], ah, bh);
                mma_bf16(acc[ni], ah, bl);
                mma_bf16(acc[ni], al, bh);
            }
        }
        __syncthreads();
        if (c + 2 < 32) stageB(c + 2);
    }

    #pragma unroll
    for (int ni = 0; ni < 8; ni++) {
        const int r = m0 + wm + (l >> 2);
        const int cc = ni * 8 + 2 * (l & 3);
        uint32_t* dst = AOp + ((size_t)b * SS + r) * DD + h * HDim + cc;
        *(uint2*)dst = make_uint2(packf(acc[ni][0]), packf(acc[ni][1]));
        *(uint2*)(dst + 8 * DD) = make_uint2(packf(acc[ni][2]), packf(acc[ni][3]));
    }
}

// ---------------------------------------------------------------------------
// Row softmax in-place (fp32 P), one block per 2048-row.
// ---------------------------------------------------------------------------
__global__ __launch_bounds__(256) void softmax_kernel(float* __restrict__ P)
{
    const size_t row = blockIdx.x;
    float4* p = (float4*)(P + row * (size_t)SS);
    const int t = threadIdx.x;
    float4 a = p[t];
    float4 b = p[t + 256];
    float mx = fmaxf(fmaxf(fmaxf(a.x, a.y), fmaxf(a.z, a.w)),
                     fmaxf(fmaxf(b.x, b.y), fmaxf(b.z, b.w)));
    #pragma unroll
    for (int o = 16; o > 0; o >>= 1) mx = fmaxf(mx, __shfl_xor_sync(0xFFFFFFFFu, mx, o));
    __shared__ float rmax[8], rsum[8];
    if ((t & 31) == 0) rmax[t >> 5] = mx;
    __syncthreads();
    mx = fmaxf(fmaxf(fmaxf(rmax[0], rmax[1]), fmaxf(rmax[2], rmax[3])),
               fmaxf(fmaxf(rmax[4], rmax[5]), fmaxf(rmax[6], rmax[7])));
    a.x = __expf(a.x - mx); a.y = __expf(a.y - mx);
    a.z = __expf(a.z - mx); a.w = __expf(a.w - mx);
    b.x = __expf(b.x - mx); b.y = __expf(b.y - mx);
    b.z = __expf(b.z - mx); b.w = __expf(b.w - mx);
    float s = a.x + a.y + a.z + a.w + b.x + b.y + b.z + b.w;
    #pragma unroll
    for (int o = 16; o > 0; o >>= 1) s += __shfl_xor_sync(0xFFFFFFFFu, s, o);
    if ((t & 31) == 0) rsum[t >> 5] = s;
    __syncthreads();
    s = rsum[0] + rsum[1] + rsum[2] + rsum[3] + rsum[4] + rsum[5] + rsum[6] + rsum[7];
    const float inv = 1.0f / s;
    a.x *= inv; a.y *= inv; a.z *= inv; a.w *= inv;
    b.x *= inv; b.y *= inv; b.z *= inv; b.w *= inv;
    p[t] = a;
    p[t + 256] = b;
}

// ---------------------------------------------------------------------------
extern "C" void kernel_launch(void* const* d_in, const int* in_sizes, int n_in,
                              void* d_out, int out_size)
{
    const float* query = (const float*)d_in[0];
    const float* key_  = (const float*)d_in[1];
    const float* value = (const float*)d_in[2];
    const float* wq = (const float*)d_in[3];
    const float* bq = (const float*)d_in[4];
    const float* wk = (const float*)d_in[5];
    const float* bk = (const float*)d_in[6];
    const float* wv = (const float*)d_in[7];
    const float* bv = (const float*)d_in[8];
    const float* wo = (const float*)d_in[9];
    const float* bo = (const float*)d_in[10];

    float* out = (float*)d_out;                 // (B,S,D)
    float* attnw = out + (size_t)BB * SS * DD;  // (B,H,S,S)

    uint32_t *xq, *xk, *xv, *pwq, *pwk, *pwv, *pwo, *qp, *kp, *vt, *aop;
    cudaGetSymbolAddress((void**)&xq, g_xq);
    cudaGetSymbolAddress((void**)&xk, g_xk);
    cudaGetSymbolAddress((void**)&xv, g_xv);
    cudaGetSymbolAddress((void**)&pwq, g_wq);
    cudaGetSymbolAddress((void**)&pwk, g_wk);
    cudaGetSymbolAddress((void**)&pwv, g_wv);
    cudaGetSymbolAddress((void**)&pwo, g_wo);
    cudaGetSymbolAddress((void**)&qp, g_qp);
    cudaGetSymbolAddress((void**)&kp, g_kp);
    cudaGetSymbolAddress((void**)&vt, g_vt);
    cudaGetSymbolAddress((void**)&aop, g_aop);

    cudaFuncSetAttribute(proj_mma,   cudaFuncAttributeMaxDynamicSharedMemorySize, PJ_SM);
    cudaFuncSetAttribute(scores_mma, cudaFuncAttributeMaxDynamicSharedMemorySize, SC_SM);
    cudaFuncSetAttribute(av_mma,     cudaFuncAttributeMaxDynamicSharedMemorySize, AV_SM);

    const int nin4 = (BB * SS * DD) / 4;   // 1048576
    const int nw4  = (DD * DD) / 4;        // 262144
    pack3_kernel<<<dim3(nin4 / 256, 3), 256>>>(
        (const float4*)query, (const float4*)key_, (const float4*)value,
        (uint4*)xq, (uint4*)xk, (uint4*)xv, nin4);
    pack4_kernel<<<dim3(nw4 / 256, 4), 256>>>(
        (const float4*)wq, (const float4*)wk, (const float4*)wv, (const float4*)wo,
        (uint4*)pwq, (uint4*)pwk, (uint4*)pwv, (uint4*)pwo, nw4);

    // Merged Q/K/V projection: one launch, blockIdx.z selects operands.
    PJArgs qkv;
    qkv.X[0] = xq;  qkv.W[0] = pwq; qkv.Bs[0] = bq; qkv.Y[0] = qp;  qkv.mode[0] = 0;
    qkv.X[1] = xk;  qkv.W[1] = pwk; qkv.Bs[1] = bk; qkv.Y[1] = kp;  qkv.mode[1] = 0;
    qkv.X[2] = xv;  qkv.W[2] = pwv; qkv.Bs[2] = bv; qkv.Y[2] = vt;  qkv.mode[2] = 1;
    proj_mma<<<dim3(DD / 64, (BB * SS) / 128, 3), 256, PJ_SM>>>(qkv);

    scores_mma<<<dim3(SS / 64, NHZ), 256, SC_SM>>>(qp, kp, attnw);

    softmax_kernel<<<NHZ * SS, 256>>>(attnw);

    av_mma<<<dim3(SS / 128, NHZ), 256, AV_SM>>>(attnw, vt, aop);

    // Final O projection (mode 2), same kernel, grid.z = 1.
    PJArgs oargs;
    oargs.X[0] = aop; oargs.W[0] = pwo; oargs.Bs[0] = bo; oargs.Y[0] = out; oargs.mode[0] = 2;
    oargs.X[1] = aop; oargs.W[1] = pwo; oargs.Bs[1] = bo; oargs.Y[1] = out; oargs.mode[1] = 2;
    oargs.X[2] = aop; oargs.W[2] = pwo; oargs.Bs[2] = bo; oargs.Y[2] = out; oargs.mode[2] = 2;
    proj_mma<<<dim3(DD / 64, (BB * SS) / 128, 1), 256, PJ_SM>>>(oargs);
}